// round 3
// baseline (speedup 1.0000x reference)
#include <cuda_runtime.h>

// Modelev12: 2-layer LSTM, H=48, B=4096, T=512, F=64 — packed-f32x2 version
#define H      48
#define TOBS   512
#define FPRED  64
#define TTOT   (TOBS + FPRED)     // 576
#define BATCH  4096
#define MB     32                 // batch rows per CTA
#define NCTA   (BATCH / MB)       // 128
#define NTHR   256                // 8 warps -> 2/SMSP

typedef unsigned long long ull;

// shared memory layout (float offsets; all ull regions at even float offsets)
#define OFF_WTP0 0                       // ull[48*96]   row-paired Whh0^T
#define OFF_WTP1 9216                    // ull[96*96]   row-paired [Wih1|Whh1]^T
#define OFF_WI0P 27648                   // ull[96]      row-paired Wih0 column
#define OFF_B0P  27840                   // ull[96]
#define OFF_B1P  28032                   // ull[96]
#define OFF_WL   28224                   // float[48]
#define OFF_HC2  28272                   // float[32][192]: {h,h} duplicated, k=0..95
#define OFF_H1   (28272 + 6144)         // float[32*49]: plain h1 for head (stride 49)
#define OFF_XC   (OFF_H1 + 1568)        // float[32]
#define OFF_GT   (OFF_XC + 48)          // float[32][192] gate pre-activations (pad to even)
#define SMEM_FLOATS (OFF_GT + 32*192)
#define SMEM_BYTES  (SMEM_FLOATS * 4)   // ~169 KB

__device__ __forceinline__ ull ffma2(ull a, ull b, ull c) {
    ull d;
    asm("fma.rn.f32x2 %0, %1, %2, %3;" : "=l"(d) : "l"(a), "l"(b), "l"(c));
    return d;
}
__device__ __forceinline__ ull pack1(float v) {           // {v, v}
    ull d; asm("mov.b64 %0, {%1, %1};" : "=l"(d) : "f"(v)); return d;
}
__device__ __forceinline__ ull pack2(float lo, float hi) { // {lo, hi}
    ull d; asm("mov.b64 %0, {%1, %2};" : "=l"(d) : "f"(lo), "f"(hi)); return d;
}
__device__ __forceinline__ void unpack2(ull v, float& lo, float& hi) {
    asm("mov.b64 {%0, %1}, %2;" : "=f"(lo), "=f"(hi) : "l"(v));
}
__device__ __forceinline__ float fsig(float xv) {
    float e = __expf(-xv);
    return __fdividef(1.0f, 1.0f + e);
}
__device__ __forceinline__ float ftanh(float xv) {
    float a = fabsf(xv);
    float e = __expf(-2.0f * a);
    float r = __fdividef(1.0f - e, 1.0f + e);
    return copysignf(r, xv);
}

__global__ void __launch_bounds__(NTHR, 1) lstm576_f32x2_kernel(
    const float* __restrict__ x,
    const float* __restrict__ wih0, const float* __restrict__ whh0,
    const float* __restrict__ bih0, const float* __restrict__ bhh0,
    const float* __restrict__ wih1, const float* __restrict__ whh1,
    const float* __restrict__ bih1, const float* __restrict__ bhh1,
    const float* __restrict__ wlin, const float* __restrict__ blin,
    float* __restrict__ out)
{
    extern __shared__ float sm[];
    ull*   WTP0 = (ull*)(sm + OFF_WTP0);
    ull*   WTP1 = (ull*)(sm + OFF_WTP1);
    ull*   WI0P = (ull*)(sm + OFF_WI0P);
    ull*   B0P  = (ull*)(sm + OFF_B0P);
    ull*   B1P  = (ull*)(sm + OFF_B1P);
    float* WLs  = sm + OFF_WL;
    float* HC2  = sm + OFF_HC2;
    float* H1s  = sm + OFF_H1;
    float* XCs  = sm + OFF_XC;
    float* GTs  = sm + OFF_GT;

    const int tid = threadIdx.x;
    const int rg  = tid & 31;       // lane: row pairs (rg+64p, rg+64p+32), p=0..2
    const int bgr = tid >> 5;       // warp: 4-batch group
    const int bb0 = bgr * 4;
    const int gb0 = blockIdx.x * MB;

    // ---- one-time staging: row-paired transposed weights ----
    for (int i = tid; i < 48 * 96; i += NTHR) {
        int k = i / 96, pr = i - k * 96;
        int r0 = (pr & 31) + 64 * (pr >> 5), r1 = r0 + 32;
        WTP0[i] = pack2(whh0[r0 * 48 + k], whh0[r1 * 48 + k]);
    }
    for (int i = tid; i < 96 * 96; i += NTHR) {
        int k = i / 96, pr = i - k * 96;
        int r0 = (pr & 31) + 64 * (pr >> 5), r1 = r0 + 32;
        float v0 = (k < 48) ? wih1[r0 * 48 + k] : whh1[r0 * 48 + (k - 48)];
        float v1 = (k < 48) ? wih1[r1 * 48 + k] : whh1[r1 * 48 + (k - 48)];
        WTP1[i] = pack2(v0, v1);
    }
    if (tid < 96) {
        int r0 = (tid & 31) + 64 * (tid >> 5), r1 = r0 + 32;
        WI0P[tid] = pack2(wih0[r0], wih0[r1]);
        B0P[tid]  = pack2(bih0[r0] + bhh0[r0], bih0[r1] + bhh0[r1]);
        B1P[tid]  = pack2(bih1[r0] + bhh1[r0], bih1[r1] + bhh1[r1]);
    }
    if (tid < 48) WLs[tid] = wlin[tid];
    for (int i = tid; i < 32 * 192; i += NTHR) HC2[i] = 0.0f;
    for (int i = tid; i < 32 * 49;  i += NTHR) H1s[i] = 0.0f;
    if (tid < MB) XCs[tid] = x[(size_t)(gb0 + tid) * TOBS];
    const float blv = blin[0];

    // activation ownership: h-element e = b*48 + j, thread owns e = tid + 256*i
    float c0r[6], c1r[6];
    int eb[6], ej[6];
#pragma unroll
    for (int i = 0; i < 6; i++) {
        c0r[i] = 0.0f; c1r[i] = 0.0f;
        int e = tid + NTHR * i;
        eb[i] = e / 48; ej[i] = e - 48 * eb[i];
    }
    __syncthreads();

    ull acc2[3][4];

    for (int t = 0; t < TTOT; t++) {
        float xnext = 0.0f;
        if (tid < MB && (t + 1) < TOBS)
            xnext = x[(size_t)(gb0 + tid) * TOBS + (t + 1)];

        // ============ layer 0: gates0 = Whh0 @ h0 + Wih0*x + b ============
        {
            ull xx[4];
#pragma unroll
            for (int bi = 0; bi < 4; bi++) xx[bi] = pack1(XCs[bb0 + bi]);
#pragma unroll
            for (int p = 0; p < 3; p++) {
                ull wi = WI0P[p * 32 + rg], bs = B0P[p * 32 + rg];
#pragma unroll
                for (int bi = 0; bi < 4; bi++) acc2[p][bi] = ffma2(wi, xx[bi], bs);
            }
#pragma unroll 4
            for (int kt = 0; kt < 48; kt += 4) {
                ulonglong2 hq[4][2];            // {h,h} duplicated pairs, 2 k per load
#pragma unroll
                for (int bi = 0; bi < 4; bi++) {
                    const ulonglong2* hp =
                        (const ulonglong2*)(HC2 + (bb0 + bi) * 192 + 2 * kt);
                    hq[bi][0] = hp[0]; hq[bi][1] = hp[1];
                }
#pragma unroll
                for (int d = 0; d < 4; d++) {
                    ull w[3];
#pragma unroll
                    for (int p = 0; p < 3; p++)
                        w[p] = WTP0[(kt + d) * 96 + p * 32 + rg];
#pragma unroll
                    for (int bi = 0; bi < 4; bi++) {
                        ull hh = (d == 0) ? hq[bi][0].x : (d == 1) ? hq[bi][0].y
                               : (d == 2) ? hq[bi][1].x : hq[bi][1].y;
#pragma unroll
                        for (int p = 0; p < 3; p++)
                            acc2[p][bi] = ffma2(w[p], hh, acc2[p][bi]);
                    }
                }
            }
#pragma unroll
            for (int p = 0; p < 3; p++)
#pragma unroll
                for (int bi = 0; bi < 4; bi++) {
                    float g0, g1; unpack2(acc2[p][bi], g0, g1);
                    GTs[(bb0 + bi) * 192 + rg + 64 * p]      = g0;
                    GTs[(bb0 + bi) * 192 + rg + 64 * p + 32] = g1;
                }
        }
        __syncthreads();

        // ---- layer 0 activations ----
#pragma unroll
        for (int i = 0; i < 6; i++) {
            const float* g4 = GTs + eb[i] * 192 + ej[i];
            float ii = fsig(g4[0]);
            float ff = fsig(g4[48]);
            float gg = ftanh(g4[96]);
            float oo = fsig(g4[144]);
            float c  = fmaf(ff, c0r[i], ii * gg);
            c0r[i]   = c;
            float h  = oo * ftanh(c);
            *(ull*)(HC2 + eb[i] * 192 + 2 * ej[i]) = pack1(h);   // h0 slot k=ej
        }
        __syncthreads();

        // ============ layer 1: gates1 = [Wih1|Whh1] @ [h0; h1] + b ============
        {
#pragma unroll
            for (int p = 0; p < 3; p++) {
                ull bs = B1P[p * 32 + rg];
#pragma unroll
                for (int bi = 0; bi < 4; bi++) acc2[p][bi] = bs;
            }
#pragma unroll 4
            for (int kt = 0; kt < 96; kt += 4) {
                ulonglong2 hq[4][2];
#pragma unroll
                for (int bi = 0; bi < 4; bi++) {
                    const ulonglong2* hp =
                        (const ulonglong2*)(HC2 + (bb0 + bi) * 192 + 2 * kt);
                    hq[bi][0] = hp[0]; hq[bi][1] = hp[1];
                }
#pragma unroll
                for (int d = 0; d < 4; d++) {
                    ull w[3];
#pragma unroll
                    for (int p = 0; p < 3; p++)
                        w[p] = WTP1[(kt + d) * 96 + p * 32 + rg];
#pragma unroll
                    for (int bi = 0; bi < 4; bi++) {
                        ull hh = (d == 0) ? hq[bi][0].x : (d == 1) ? hq[bi][0].y
                               : (d == 2) ? hq[bi][1].x : hq[bi][1].y;
#pragma unroll
                        for (int p = 0; p < 3; p++)
                            acc2[p][bi] = ffma2(w[p], hh, acc2[p][bi]);
                    }
                }
            }
#pragma unroll
            for (int p = 0; p < 3; p++)
#pragma unroll
                for (int bi = 0; bi < 4; bi++) {
                    float g0, g1; unpack2(acc2[p][bi], g0, g1);
                    GTs[(bb0 + bi) * 192 + rg + 64 * p]      = g0;
                    GTs[(bb0 + bi) * 192 + rg + 64 * p + 32] = g1;
                }
        }
        __syncthreads();

        // ---- layer 1 activations ----
#pragma unroll
        for (int i = 0; i < 6; i++) {
            const float* g4 = GTs + eb[i] * 192 + ej[i];
            float ii = fsig(g4[0]);
            float ff = fsig(g4[48]);
            float gg = ftanh(g4[96]);
            float oo = fsig(g4[144]);
            float c  = fmaf(ff, c1r[i], ii * gg);
            c1r[i]   = c;
            float h  = oo * ftanh(c);
            *(ull*)(HC2 + eb[i] * 192 + 96 + 2 * ej[i]) = pack1(h); // h1 slot k=48+ej
            H1s[eb[i] * 49 + ej[i]] = h;                            // plain copy for head
        }
        __syncthreads();

        // ---- output head + next-step input ----
        if (tid < MB) {
            const float* h1 = H1s + tid * 49;
            float s0 = 0.f, s1 = 0.f, s2 = 0.f, s3 = 0.f;
#pragma unroll
            for (int k = 0; k < 48; k += 4) {
                s0 = fmaf(h1[k],     WLs[k],     s0);
                s1 = fmaf(h1[k + 1], WLs[k + 1], s1);
                s2 = fmaf(h1[k + 2], WLs[k + 2], s2);
                s3 = fmaf(h1[k + 3], WLs[k + 3], s3);
            }
            float s = (s0 + s1) + (s2 + s3) + blv;
            out[(size_t)(gb0 + tid) * TTOT + t] = s;
            XCs[tid] = ((t + 1) < TOBS) ? xnext : s;
        }
        __syncthreads();
    }
}

extern "C" void kernel_launch(void* const* d_in, const int* in_sizes, int n_in,
                              void* d_out, int out_size)
{
    (void)in_sizes; (void)n_in; (void)out_size;
    const float* x    = (const float*)d_in[0];
    const float* wih0 = (const float*)d_in[1];
    const float* whh0 = (const float*)d_in[2];
    const float* bih0 = (const float*)d_in[3];
    const float* bhh0 = (const float*)d_in[4];
    const float* wih1 = (const float*)d_in[5];
    const float* whh1 = (const float*)d_in[6];
    const float* bih1 = (const float*)d_in[7];
    const float* bhh1 = (const float*)d_in[8];
    const float* wlin = (const float*)d_in[9];
    const float* blin = (const float*)d_in[10];
    float* out = (float*)d_out;

    cudaFuncSetAttribute(lstm576_f32x2_kernel,
                         cudaFuncAttributeMaxDynamicSharedMemorySize, SMEM_BYTES);
    lstm576_f32x2_kernel<<<NCTA, NTHR, SMEM_BYTES>>>(
        x, wih0, whh0, bih0, bhh0, wih1, whh1, bih1, bhh1, wlin, blin, out);
}

// round 5
// speedup vs baseline: 1.2154x; 1.2154x over previous
#include <cuda_runtime.h>

// Modelev12: 2-layer LSTM, H=48, B=4096, T=512, F=64
// Batch-paired fma.rn.f32x2, scalar weight loads, row-split warps.
// R4 fix: OFF_XC alignment (was odd float offset -> misaligned LDS.64).
#define H      48
#define TOBS   512
#define FPRED  64
#define TTOT   (TOBS + FPRED)     // 576
#define BATCH  4096
#define MB     32                 // batch rows per CTA
#define NCTA   (BATCH / MB)       // 128
#define NTHR   256                // 8 warps = 4 batch-groups x 2 row-halves

typedef unsigned long long ull;

// shared layout (float offsets; all vector-accessed blocks 16B-aligned)
#define OFF_WT0 0                        // [48*192]  Whh0^T   (WT0[k*192+r])
#define OFF_WT1 (OFF_WT0 + 48*192)       // [96*192]  [Wih1|Whh1]^T
#define OFF_WI0 (OFF_WT1 + 96*192)       // [192]
#define OFF_B0  (OFF_WI0 + 192)          // [192]
#define OFF_B1  (OFF_B0 + 192)           // [192]
#define OFF_WL  (OFF_B1 + 192)           // [48]
#define OFF_HC2 (OFF_WL + 48)            // [96][36]  h state, HC2[k*36+b]; 28272 % 4 == 0
#define OFF_H1  (OFF_HC2 + 96*36)        // [32*49]   plain h1 for head; 31728
#define OFF_XC  (OFF_H1 + 32*49)         // [32]      33296 % 4 == 0 -> 16B aligned
#define OFF_GT  (OFF_XC + 32)            // [32][192] gate pre-activations
#define SMEM_FLOATS (OFF_GT + 32*192)
#define SMEM_BYTES  (SMEM_FLOATS * 4)

__device__ __forceinline__ ull ffma2(ull a, ull b, ull c) {
    ull d;
    asm("fma.rn.f32x2 %0, %1, %2, %3;" : "=l"(d) : "l"(a), "l"(b), "l"(c));
    return d;
}
__device__ __forceinline__ ull pack1(float v) {            // {v, v}
    ull d; asm("mov.b64 %0, {%1, %1};" : "=l"(d) : "f"(v)); return d;
}
__device__ __forceinline__ void unpack2(ull v, float& lo, float& hi) {
    asm("mov.b64 {%0, %1}, %2;" : "=f"(lo), "=f"(hi) : "l"(v));
}
__device__ __forceinline__ float fsig(float xv) {
    float e = __expf(-xv);
    return __fdividef(1.0f, 1.0f + e);
}
__device__ __forceinline__ float ftanh(float xv) {
    float a = fabsf(xv);
    float e = __expf(-2.0f * a);
    float r = __fdividef(1.0f - e, 1.0f + e);
    return copysignf(r, xv);
}

__global__ void __launch_bounds__(NTHR, 1) lstm576_bp2_kernel(
    const float* __restrict__ x,
    const float* __restrict__ wih0, const float* __restrict__ whh0,
    const float* __restrict__ bih0, const float* __restrict__ bhh0,
    const float* __restrict__ wih1, const float* __restrict__ whh1,
    const float* __restrict__ bih1, const float* __restrict__ bhh1,
    const float* __restrict__ wlin, const float* __restrict__ blin,
    float* __restrict__ out)
{
    extern __shared__ float sm[];
    float* WT0 = sm + OFF_WT0;
    float* WT1 = sm + OFF_WT1;
    float* WI0 = sm + OFF_WI0;
    float* B0s = sm + OFF_B0;
    float* B1s = sm + OFF_B1;
    float* WLs = sm + OFF_WL;
    float* HC2 = sm + OFF_HC2;   // HC2[k*36 + b]
    float* H1s = sm + OFF_H1;
    float* XCs = sm + OFF_XC;
    float* GTs = sm + OFF_GT;

    const int tid = threadIdx.x;
    const int rg  = tid & 31;
    const int w   = tid >> 5;
    const int bg  = w >> 1;          // batch group: batches 8*bg .. 8*bg+7
    const int rh  = w & 1;           // row half: rows 96*rh .. 96*rh+95
    const int rbase = 96 * rh + rg;  // rows rbase, rbase+32, rbase+64
    const int gb0 = blockIdx.x * MB;
    const int bloc = 8 * bg;         // local batch base for this warp

    // ---- one-time staging ----
    for (int i = tid; i < 48 * 192; i += NTHR) {
        int k = i / 192, r = i - k * 192;
        WT0[i] = whh0[r * 48 + k];
    }
    for (int i = tid; i < 96 * 192; i += NTHR) {
        int k = i / 192, r = i - k * 192;
        WT1[i] = (k < 48) ? wih1[r * 48 + k] : whh1[r * 48 + (k - 48)];
    }
    for (int i = tid; i < 192; i += NTHR) {
        WI0[i] = wih0[i];
        B0s[i] = bih0[i] + bhh0[i];
        B1s[i] = bih1[i] + bhh1[i];
    }
    if (tid < 48) WLs[tid] = wlin[tid];
    for (int i = tid; i < 96 * 36; i += NTHR) HC2[i] = 0.0f;
    for (int i = tid; i < 32 * 49; i += NTHR) H1s[i] = 0.0f;
    if (tid < MB) XCs[tid] = x[(size_t)(gb0 + tid) * TOBS];
    const float blv = blin[0];

    // activation ownership: element e = b*48 + j, thread owns e = tid + 256*i
    float c0r[6], c1r[6];
    int eb[6], ej[6];
#pragma unroll
    for (int i = 0; i < 6; i++) {
        c0r[i] = 0.0f; c1r[i] = 0.0f;
        int e = tid + NTHR * i;
        eb[i] = e / 48; ej[i] = e - 48 * eb[i];
    }
    __syncthreads();

    ull acc2[3][4];   // [row m][batch pair bp] -> {gate[b=bloc+2bp], gate[b+1]}

    for (int t = 0; t < TTOT; t++) {
        float xnext = 0.0f;
        if (tid < MB && (t + 1) < TOBS)
            xnext = x[(size_t)(gb0 + tid) * TOBS + (t + 1)];

        // ============ layer 0: gates0 = Whh0 @ h0 + Wih0*x + b ============
        {
            ull x2[4];
#pragma unroll
            for (int bp = 0; bp < 4; bp++)
                x2[bp] = *(const ull*)(XCs + bloc + 2 * bp);     // broadcast LDS.64
#pragma unroll
            for (int m = 0; m < 3; m++) {
                int r = rbase + 32 * m;
                ull wi = pack1(WI0[r]);
                ull bs = pack1(B0s[r]);
#pragma unroll
                for (int bp = 0; bp < 4; bp++)
                    acc2[m][bp] = ffma2(wi, x2[bp], bs);
            }
#pragma unroll 4
            for (int kt = 0; kt < 48; kt += 4) {
                ulonglong2 ha[4], hb[4];
#pragma unroll
                for (int d = 0; d < 4; d++) {
                    const float* hp = HC2 + (kt + d) * 36 + bloc;
                    ha[d] = *(const ulonglong2*)(hp);            // bp 0,1
                    hb[d] = *(const ulonglong2*)(hp + 4);        // bp 2,3
                }
#pragma unroll
                for (int d = 0; d < 4; d++) {
                    ull w2[3];
#pragma unroll
                    for (int m = 0; m < 3; m++)
                        w2[m] = pack1(WT0[(kt + d) * 192 + rbase + 32 * m]);
#pragma unroll
                    for (int m = 0; m < 3; m++) {
                        acc2[m][0] = ffma2(w2[m], ha[d].x, acc2[m][0]);
                        acc2[m][1] = ffma2(w2[m], ha[d].y, acc2[m][1]);
                        acc2[m][2] = ffma2(w2[m], hb[d].x, acc2[m][2]);
                        acc2[m][3] = ffma2(w2[m], hb[d].y, acc2[m][3]);
                    }
                }
            }
#pragma unroll
            for (int m = 0; m < 3; m++) {
                int r = rbase + 32 * m;
#pragma unroll
                for (int bp = 0; bp < 4; bp++) {
                    float g0, g1; unpack2(acc2[m][bp], g0, g1);
                    GTs[(bloc + 2 * bp)     * 192 + r] = g0;
                    GTs[(bloc + 2 * bp + 1) * 192 + r] = g1;
                }
            }
        }
        __syncthreads();

        // ---- layer 0 activations (c in regs, h -> HC2 rows 0..47) ----
#pragma unroll
        for (int i = 0; i < 6; i++) {
            const float* g4 = GTs + eb[i] * 192 + ej[i];
            float ii = fsig(g4[0]);
            float ff = fsig(g4[48]);
            float gg = ftanh(g4[96]);
            float oo = fsig(g4[144]);
            float c  = fmaf(ff, c0r[i], ii * gg);
            c0r[i]   = c;
            HC2[ej[i] * 36 + eb[i]] = oo * ftanh(c);
        }
        __syncthreads();

        // ============ layer 1: gates1 = [Wih1|Whh1] @ [h0; h1] + b ============
        {
#pragma unroll
            for (int m = 0; m < 3; m++) {
                ull bs = pack1(B1s[rbase + 32 * m]);
#pragma unroll
                for (int bp = 0; bp < 4; bp++) acc2[m][bp] = bs;
            }
#pragma unroll 4
            for (int kt = 0; kt < 96; kt += 4) {
                ulonglong2 ha[4], hb[4];
#pragma unroll
                for (int d = 0; d < 4; d++) {
                    const float* hp = HC2 + (kt + d) * 36 + bloc;
                    ha[d] = *(const ulonglong2*)(hp);
                    hb[d] = *(const ulonglong2*)(hp + 4);
                }
#pragma unroll
                for (int d = 0; d < 4; d++) {
                    ull w2[3];
#pragma unroll
                    for (int m = 0; m < 3; m++)
                        w2[m] = pack1(WT1[(kt + d) * 192 + rbase + 32 * m]);
#pragma unroll
                    for (int m = 0; m < 3; m++) {
                        acc2[m][0] = ffma2(w2[m], ha[d].x, acc2[m][0]);
                        acc2[m][1] = ffma2(w2[m], ha[d].y, acc2[m][1]);
                        acc2[m][2] = ffma2(w2[m], hb[d].x, acc2[m][2]);
                        acc2[m][3] = ffma2(w2[m], hb[d].y, acc2[m][3]);
                    }
                }
            }
#pragma unroll
            for (int m = 0; m < 3; m++) {
                int r = rbase + 32 * m;
#pragma unroll
                for (int bp = 0; bp < 4; bp++) {
                    float g0, g1; unpack2(acc2[m][bp], g0, g1);
                    GTs[(bloc + 2 * bp)     * 192 + r] = g0;
                    GTs[(bloc + 2 * bp + 1) * 192 + r] = g1;
                }
            }
        }
        __syncthreads();

        // ---- layer 1 activations (h -> HC2 rows 48..95 + H1s for head) ----
#pragma unroll
        for (int i = 0; i < 6; i++) {
            const float* g4 = GTs + eb[i] * 192 + ej[i];
            float ii = fsig(g4[0]);
            float ff = fsig(g4[48]);
            float gg = ftanh(g4[96]);
            float oo = fsig(g4[144]);
            float c  = fmaf(ff, c1r[i], ii * gg);
            c1r[i]   = c;
            float h  = oo * ftanh(c);
            HC2[(48 + ej[i]) * 36 + eb[i]] = h;
            H1s[eb[i] * 49 + ej[i]] = h;
        }
        __syncthreads();

        // ---- output head + next-step input ----
        if (tid < MB) {
            const float* h1 = H1s + tid * 49;
            float s0 = 0.f, s1 = 0.f, s2 = 0.f, s3 = 0.f;
#pragma unroll
            for (int k = 0; k < 48; k += 4) {
                s0 = fmaf(h1[k],     WLs[k],     s0);
                s1 = fmaf(h1[k + 1], WLs[k + 1], s1);
                s2 = fmaf(h1[k + 2], WLs[k + 2], s2);
                s3 = fmaf(h1[k + 3], WLs[k + 3], s3);
            }
            float s = (s0 + s1) + (s2 + s3) + blv;
            out[(size_t)(gb0 + tid) * TTOT + t] = s;
            XCs[tid] = ((t + 1) < TOBS) ? xnext : s;
        }
        __syncthreads();
    }
}

extern "C" void kernel_launch(void* const* d_in, const int* in_sizes, int n_in,
                              void* d_out, int out_size)
{
    (void)in_sizes; (void)n_in; (void)out_size;
    const float* x    = (const float*)d_in[0];
    const float* wih0 = (const float*)d_in[1];
    const float* whh0 = (const float*)d_in[2];
    const float* bih0 = (const float*)d_in[3];
    const float* bhh0 = (const float*)d_in[4];
    const float* wih1 = (const float*)d_in[5];
    const float* whh1 = (const float*)d_in[6];
    const float* bih1 = (const float*)d_in[7];
    const float* bhh1 = (const float*)d_in[8];
    const float* wlin = (const float*)d_in[9];
    const float* blin = (const float*)d_in[10];
    float* out = (float*)d_out;

    cudaFuncSetAttribute(lstm576_bp2_kernel,
                         cudaFuncAttributeMaxDynamicSharedMemorySize, SMEM_BYTES);
    lstm576_bp2_kernel<<<NCTA, NTHR, SMEM_BYTES>>>(
        x, wih0, whh0, bih0, bhh0, wih1, whh1, bih1, bhh1, wlin, blin, out);
}